// round 15
// baseline (speedup 1.0000x reference)
#include <cuda_runtime.h>
#include <cuda_bf16.h>
#include <cstdint>

#define NB 8
#define SQ 1024
#define DIN 1280
#define RNK 64
#define DOUT 1280
#define DOWNSZ (RNK*DIN)
#define UPSZ (DOUT*RNK)
#define EMBSZ (DOWNSZ+UPSZ)

#define LDP  72           // padded row stride (bf16 elems); 144 B
#define LDPB (LDP*2)

// split-K h partials
__device__ float g_hp[2][NB*SQ*RNK];

__device__ __forceinline__ uint32_t smem_u32(const void* p) {
    uint32_t a;
    asm("{ .reg .u64 t; cvta.to.shared.u64 t, %1; cvt.u32.u64 %0, t; }" : "=r"(a) : "l"(p));
    return a;
}
// truncation split: hi = top16(a), lo = rn_bf16(a - hi)
__device__ __forceinline__ void split2f(float a, float b, uint32_t& hi, uint32_t& lo) {
    uint32_t ua = __float_as_uint(a), ub = __float_as_uint(b);
    uint32_t h;
    asm("prmt.b32 %0, %1, %2, 0x7632;" : "=r"(h) : "r"(ua), "r"(ub));
    float ra = a - __uint_as_float(ua & 0xFFFF0000u);
    float rb = b - __uint_as_float(ub & 0xFFFF0000u);
    uint32_t l;
    asm("cvt.rn.bf16x2.f32 %0, %1, %2;" : "=r"(l) : "f"(rb), "f"(ra));
    hi = h; lo = l;
}
__device__ __forceinline__ void mma16816(float* d, const uint32_t* a, const uint32_t* b) {
    asm volatile("mma.sync.aligned.m16n8k16.row.col.f32.bf16.bf16.f32 "
        "{%0,%1,%2,%3}, {%4,%5,%6,%7}, {%8,%9}, {%0,%1,%2,%3};"
        : "+f"(d[0]), "+f"(d[1]), "+f"(d[2]), "+f"(d[3])
        : "r"(a[0]), "r"(a[1]), "r"(a[2]), "r"(a[3]), "r"(b[0]), "r"(b[1]));
}
#define LDSM4(R, addr) \
    asm volatile("ldmatrix.sync.aligned.m8n8.x4.shared.b16 {%0,%1,%2,%3}, [%4];" \
        : "=r"((R)[0]), "=r"((R)[1]), "=r"((R)[2]), "=r"((R)[3]) : "r"(addr))

// ============================================================================
// k_down: UNCHANGED from R14 (20.5us; isolate the k_up experiment).
// ============================================================================
static constexpr int D_T   = 64 * LDP;            // elems per tile (4608)
static constexpr int D_BUF = 4 * D_T;             // AH AL WH WL
static constexpr int SMEM_DOWN = 2 * D_BUF * 2;   // 73728 B

__global__ __launch_bounds__(256, 2)
void k_down(const float* __restrict__ x, const float* __restrict__ embed) {
    extern __shared__ __nv_bfloat16 sm[];
    const uint32_t smb = smem_u32(sm);
    const int tid = threadIdx.x, lane = tid & 31, wid = tid >> 5;
    const int b = blockIdx.z, kcb = blockIdx.y, s0 = blockIdx.x * 64;
    const int kbase = kcb * 640;
    const float* __restrict__ xb = x     + ((size_t)b * SQ + s0) * DIN + kbase;
    const float* __restrict__ wd = embed + (size_t)b * EMBSZ + kbase;   // [r][DIN] fp32

    const int frow = tid >> 4, fcol = (tid & 15) * 4;
    const int wm = wid >> 1, wn = wid & 1;
    const int m0 = wm * 16, n0 = wn * 32;
    const int r8 = lane & 7, gq = lane >> 3;

    const uint32_t offA  = (uint32_t)(m0 + r8 + (gq & 1) * 8) * LDPB + (gq >> 1) * 16;
    const uint32_t offB0 = (uint32_t)(n0 + 0 * 8 + r8 + (gq >> 1) * 8) * LDPB + (gq & 1) * 16;
    const uint32_t offB2 = (uint32_t)(n0 + 2 * 8 + r8 + (gq >> 1) * 8) * LDPB + (gq & 1) * 16;

    float acc[4][4];
#pragma unroll
    for (int u = 0; u < 4; u++)
#pragma unroll
        for (int j = 0; j < 4; j++) acc[u][j] = 0.f;

    {
        __nv_bfloat16* AH = sm;           __nv_bfloat16* AL = sm + D_T;
        __nv_bfloat16* WH = sm + 2 * D_T; __nv_bfloat16* WL = sm + 3 * D_T;
#pragma unroll
        for (int p = 0; p < 4; p++) {
            const int row = p * 16 + frow;
            float4 v = *(const float4*)(xb + (size_t)row * DIN + fcol);
            uint32_t h0, l0, h1, l1;
            split2f(v.x, v.y, h0, l0); split2f(v.z, v.w, h1, l1);
            *(uint2*)(AH + row * LDP + fcol) = make_uint2(h0, h1);
            *(uint2*)(AL + row * LDP + fcol) = make_uint2(l0, l1);
            float4 w = *(const float4*)(wd + (size_t)row * DIN + fcol);
            split2f(w.x, w.y, h0, l0); split2f(w.z, w.w, h1, l1);
            *(uint2*)(WH + row * LDP + fcol) = make_uint2(h0, h1);
            *(uint2*)(WL + row * LDP + fcol) = make_uint2(l0, l1);
        }
    }
    __syncthreads();

    for (int it = 0; it < 10; it++) {
        const uint32_t base = smb + (it & 1) * (D_BUF * 2);
        const bool has_next = (it + 1 < 10);
        const int kc = (it + 1) * 64;
        __nv_bfloat16* nb = sm + ((it + 1) & 1) * D_BUF;

        float4 xv[4];
        if (has_next) {
#pragma unroll
            for (int p = 0; p < 4; p++)
                xv[p] = *(const float4*)(xb + (size_t)(p * 16 + frow) * DIN + kc + fcol);
        }

        const uint32_t AH = base, AL = base + 2 * D_T, WH = base + 4 * D_T, WL = base + 6 * D_T;
#pragma unroll
        for (int kk = 0; kk < 2; kk++) {
            const uint32_t ko = kk * 32;
            uint32_t aH[4], aL[4], bH[4], bL[4], bH2[4], bL2[4];
            LDSM4(aH, AH + offA + ko);
            LDSM4(aL, AL + offA + ko);
            LDSM4(bH, WH + offB0 + ko);
            LDSM4(bL, WL + offB0 + ko);
            LDSM4(bH2, WH + offB2 + ko);
            LDSM4(bL2, WL + offB2 + ko);
            mma16816(acc[0], aH, bH);      mma16816(acc[0], aH, bL);      mma16816(acc[0], aL, bH);
            mma16816(acc[1], aH, bH + 2);  mma16816(acc[1], aH, bL + 2);  mma16816(acc[1], aL, bH + 2);
            mma16816(acc[2], aH, bH2);     mma16816(acc[2], aH, bL2);     mma16816(acc[2], aL, bH2);
            mma16816(acc[3], aH, bH2 + 2); mma16816(acc[3], aH, bL2 + 2); mma16816(acc[3], aL, bH2 + 2);
        }

        float4 wv[4];
        if (has_next) {
            __nv_bfloat16* AHn = nb; __nv_bfloat16* ALn = nb + D_T;
#pragma unroll
            for (int p = 0; p < 4; p++) {
                const int row = p * 16 + frow;
                uint32_t h0, l0, h1, l1;
                split2f(xv[p].x, xv[p].y, h0, l0); split2f(xv[p].z, xv[p].w, h1, l1);
                *(uint2*)(AHn + row * LDP + fcol) = make_uint2(h0, h1);
                *(uint2*)(ALn + row * LDP + fcol) = make_uint2(l0, l1);
            }
#pragma unroll
            for (int p = 0; p < 4; p++)
                wv[p] = *(const float4*)(wd + (size_t)(p * 16 + frow) * DIN + kc + fcol);
        }

#pragma unroll
        for (int kk = 2; kk < 4; kk++) {
            const uint32_t ko = kk * 32;
            uint32_t aH[4], aL[4], bH[4], bL[4], bH2[4], bL2[4];
            LDSM4(aH, AH + offA + ko);
            LDSM4(aL, AL + offA + ko);
            LDSM4(bH, WH + offB0 + ko);
            LDSM4(bL, WL + offB0 + ko);
            LDSM4(bH2, WH + offB2 + ko);
            LDSM4(bL2, WL + offB2 + ko);
            mma16816(acc[0], aH, bH);      mma16816(acc[0], aH, bL);      mma16816(acc[0], aL, bH);
            mma16816(acc[1], aH, bH + 2);  mma16816(acc[1], aH, bL + 2);  mma16816(acc[1], aL, bH + 2);
            mma16816(acc[2], aH, bH2);     mma16816(acc[2], aH, bL2);     mma16816(acc[2], aL, bH2);
            mma16816(acc[3], aH, bH2 + 2); mma16816(acc[3], aH, bL2 + 2); mma16816(acc[3], aL, bH2 + 2);
        }

        if (has_next) {
            __nv_bfloat16* WHn = nb + 2 * D_T; __nv_bfloat16* WLn = nb + 3 * D_T;
#pragma unroll
            for (int p = 0; p < 4; p++) {
                const int row = p * 16 + frow;
                uint32_t h0, l0, h1, l1;
                split2f(wv[p].x, wv[p].y, h0, l0); split2f(wv[p].z, wv[p].w, h1, l1);
                *(uint2*)(WHn + row * LDP + fcol) = make_uint2(h0, h1);
                *(uint2*)(WLn + row * LDP + fcol) = make_uint2(l0, l1);
            }
            __syncthreads();
        }
    }

    float* hp = g_hp[kcb] + ((size_t)b * SQ + s0) * RNK;
    const int g = lane >> 2, tg = lane & 3;
#pragma unroll
    for (int u = 0; u < 4; u++) {
        const int c = n0 + u * 8 + tg * 2;
        *(float2*)(hp + (size_t)(m0 + g) * RNK + c)     = make_float2(acc[u][0], acc[u][1]);
        *(float2*)(hp + (size_t)(m0 + g + 8) * RNK + c) = make_float2(acc[u][2], acc[u][3]);
    }
}

// ============================================================================
// k_up: out = h @ w_up^T.  NEW: 4 s-tiles per CTA reuse one W fill; h tile
// double-buffered (raw LDG prefetch held across MMA).  8 warps (2m x 4n).
// grid (4 s-groups, 10 o, 8 b) = 320 CTAs, 256 thr.
// ============================================================================
static constexpr int U_HT = 64 * LDP;
static constexpr int U_WT = 128 * LDP;
static constexpr int SMEM_UP = (4 * U_HT + 2 * U_WT) * 2;  // 73728 B

__global__ __launch_bounds__(256, 2)
void k_up(const float* __restrict__ embed, float* __restrict__ out) {
    extern __shared__ __nv_bfloat16 sm[];
    const uint32_t smb = smem_u32(sm);
    __nv_bfloat16* WH = sm + 4 * U_HT;
    __nv_bfloat16* WL = sm + 4 * U_HT + U_WT;

    const int tid = threadIdx.x, lane = tid & 31, wid = tid >> 5;
    const int b = blockIdx.z, s0 = blockIdx.x * 256, o0 = blockIdx.y * 128;
    const float* __restrict__ h0p = g_hp[0] + ((size_t)b * SQ + s0) * RNK;
    const float* __restrict__ h1p = g_hp[1] + ((size_t)b * SQ + s0) * RNK;
    const float* __restrict__ wp  = embed + (size_t)b * EMBSZ + DOWNSZ
                                    + (size_t)o0 * RNK;              // [o][r] fp32

    const int frow = tid >> 4, fcol = (tid & 15) * 4;
    // W fill: 128 rows x 64 cols fp32, inline split (8 passes) -- ONCE per CTA
#pragma unroll
    for (int p = 0; p < 8; p++) {
        const int row = p * 16 + frow;
        float4 v = *(const float4*)(wp + (size_t)row * RNK + fcol);
        uint32_t h0, l0, h1, l1;
        split2f(v.x, v.y, h0, l0); split2f(v.z, v.w, h1, l1);
        *(uint2*)(WH + row * LDP + fcol) = make_uint2(h0, h1);
        *(uint2*)(WL + row * LDP + fcol) = make_uint2(l0, l1);
    }
    // h tile 0 fill into buffer 0
    {
        __nv_bfloat16* HH = sm; __nv_bfloat16* HL = sm + U_HT;
#pragma unroll
        for (int p = 0; p < 4; p++) {
            const int row = p * 16 + frow;
            float4 a = *(const float4*)(h0p + (size_t)row * RNK + fcol);
            float4 c = *(const float4*)(h1p + (size_t)row * RNK + fcol);
            uint32_t h0, l0, h1, l1;
            split2f(a.x + c.x, a.y + c.y, h0, l0);
            split2f(a.z + c.z, a.w + c.w, h1, l1);
            *(uint2*)(HH + row * LDP + fcol) = make_uint2(h0, h1);
            *(uint2*)(HL + row * LDP + fcol) = make_uint2(l0, l1);
        }
    }
    __syncthreads();

    const int wm = wid >> 2, wn = wid & 3;
    const int m0 = wm * 32, n0 = wn * 32;
    const int r8 = lane & 7, gq = lane >> 3;
    const int g = lane >> 2, tg = lane & 3;

    const uint32_t WHa = smb + 4 * U_HT * 2, WLa = WHa + U_WT * 2;
    const uint32_t offA0 = (uint32_t)(m0 + r8 + (gq & 1) * 8) * LDPB + (gq >> 1) * 16;
    const uint32_t offA1 = offA0 + 16 * LDPB;
    const uint32_t offB0 = (uint32_t)(n0 + r8 + (gq >> 1) * 8) * LDPB + (gq & 1) * 16;
    const uint32_t offB2 = offB0 + 16 * LDPB;

    for (int st = 0; st < 4; st++) {
        const int cur = st & 1;
        const uint32_t HHa = smb + cur * (2 * U_HT * 2);
        const uint32_t HLa = HHa + U_HT * 2;

        // prefetch next h tile (raw; MMA below covers the LDG latency)
        float4 av[4], cv[4];
        const bool has_next = (st + 1 < 4);
        if (has_next) {
            const size_t roff = (size_t)(st + 1) * 64;
#pragma unroll
            for (int p = 0; p < 4; p++) {
                const size_t row = roff + p * 16 + frow;
                av[p] = *(const float4*)(h0p + row * RNK + fcol);
                cv[p] = *(const float4*)(h1p + row * RNK + fcol);
            }
        }

        float acc[2][4][4];
#pragma unroll
        for (int t = 0; t < 2; t++)
#pragma unroll
            for (int u = 0; u < 4; u++)
#pragma unroll
                for (int j = 0; j < 4; j++) acc[t][u][j] = 0.f;

#pragma unroll
        for (int kk = 0; kk < 4; kk++) {
            const uint32_t ko = kk * 32;
            uint32_t aH0[4], aL0[4], aH1[4], aL1[4];
            uint32_t bH[4], bL[4], bH2[4], bL2[4];
            LDSM4(aH0, HHa + offA0 + ko);
            LDSM4(aL0, HLa + offA0 + ko);
            LDSM4(aH1, HHa + offA1 + ko);
            LDSM4(aL1, HLa + offA1 + ko);
            LDSM4(bH, WHa + offB0 + ko);
            LDSM4(bL, WLa + offB0 + ko);
            LDSM4(bH2, WHa + offB2 + ko);
            LDSM4(bL2, WLa + offB2 + ko);
#pragma unroll
            for (int t = 0; t < 2; t++) {
                const uint32_t* aH = t ? aH1 : aH0;
                const uint32_t* aL = t ? aL1 : aL0;
                mma16816(acc[t][0], aH, bH);      mma16816(acc[t][0], aH, bL);      mma16816(acc[t][0], aL, bH);
                mma16816(acc[t][1], aH, bH + 2);  mma16816(acc[t][1], aH, bL + 2);  mma16816(acc[t][1], aL, bH + 2);
                mma16816(acc[t][2], aH, bH2);     mma16816(acc[t][2], aH, bL2);     mma16816(acc[t][2], aL, bH2);
                mma16816(acc[t][3], aH, bH2 + 2); mma16816(acc[t][3], aH, bL2 + 2); mma16816(acc[t][3], aL, bH2 + 2);
            }
        }

        // epilogue for this s-tile
#pragma unroll
        for (int t = 0; t < 2; t++) {
            const size_t r0 = (size_t)b * SQ + s0 + st * 64 + m0 + t * 16 + g;
#pragma unroll
            for (int u = 0; u < 4; u++) {
                const int c = o0 + n0 + u * 8 + tg * 2;
                *(float2*)(out + r0 * DOUT + c)       = make_float2(acc[t][u][0], acc[t][u][1]);
                *(float2*)(out + (r0 + 8) * DOUT + c) = make_float2(acc[t][u][2], acc[t][u][3]);
            }
        }

        if (has_next) {
            __syncthreads();   // all warps done reading buf cur^1 (tile st-1)
            __nv_bfloat16* HHn = sm + (cur ^ 1) * (2 * U_HT);
            __nv_bfloat16* HLn = HHn + U_HT;
#pragma unroll
            for (int p = 0; p < 4; p++) {
                const int row = p * 16 + frow;
                uint32_t h0, l0, h1, l1;
                split2f(av[p].x + cv[p].x, av[p].y + cv[p].y, h0, l0);
                split2f(av[p].z + cv[p].z, av[p].w + cv[p].w, h1, l1);
                *(uint2*)(HHn + row * LDP + fcol) = make_uint2(h0, h1);
                *(uint2*)(HLn + row * LDP + fcol) = make_uint2(l0, l1);
            }
            __syncthreads();   // STS visible before next tile's MMA
        }
    }
}

extern "C" void kernel_launch(void* const* d_in, const int* in_sizes, int n_in,
                              void* d_out, int out_size) {
    const float* x     = (const float*)d_in[0];   // [8,1024,1280]
    const float* embed = (const float*)d_in[1];   // [8,163840]
    float*       out   = (float*)d_out;           // [8,1024,1280]
    (void)in_sizes; (void)n_in; (void)out_size;

    cudaFuncSetAttribute(k_down, cudaFuncAttributeMaxDynamicSharedMemorySize, SMEM_DOWN);
    cudaFuncSetAttribute(k_up,   cudaFuncAttributeMaxDynamicSharedMemorySize, SMEM_UP);

    k_down<<<dim3(16, 2, 8), 256, SMEM_DOWN>>>(x, embed);
    k_up<<<dim3(4, 10, 8), 256, SMEM_UP>>>(embed, out);
}

// round 17
// speedup vs baseline: 1.0437x; 1.0437x over previous
#include <cuda_runtime.h>
#include <cuda_bf16.h>
#include <cstdint>

#define NB 8
#define SQ 1024
#define DIN 1280
#define RNK 64
#define DOUT 1280
#define DOWNSZ (RNK*DIN)
#define UPSZ (DOUT*RNK)
#define EMBSZ (DOWNSZ+UPSZ)

#define LDP  72           // padded row stride (bf16 elems); 144 B
#define LDPB (LDP*2)

// split-K h partials
__device__ float g_hp[2][NB*SQ*RNK];

__device__ __forceinline__ uint32_t smem_u32(const void* p) {
    uint32_t a;
    asm("{ .reg .u64 t; cvta.to.shared.u64 t, %1; cvt.u32.u64 %0, t; }" : "=r"(a) : "l"(p));
    return a;
}
// truncation split: hi = top16(a), lo = rn_bf16(a - hi)
__device__ __forceinline__ void split2f(float a, float b, uint32_t& hi, uint32_t& lo) {
    uint32_t ua = __float_as_uint(a), ub = __float_as_uint(b);
    uint32_t h;
    asm("prmt.b32 %0, %1, %2, 0x7632;" : "=r"(h) : "r"(ua), "r"(ub));
    float ra = a - __uint_as_float(ua & 0xFFFF0000u);
    float rb = b - __uint_as_float(ub & 0xFFFF0000u);
    uint32_t l;
    asm("cvt.rn.bf16x2.f32 %0, %1, %2;" : "=r"(l) : "f"(rb), "f"(ra));
    hi = h; lo = l;
}
__device__ __forceinline__ void mma16816(float* d, const uint32_t* a, const uint32_t* b) {
    asm volatile("mma.sync.aligned.m16n8k16.row.col.f32.bf16.bf16.f32 "
        "{%0,%1,%2,%3}, {%4,%5,%6,%7}, {%8,%9}, {%0,%1,%2,%3};"
        : "+f"(d[0]), "+f"(d[1]), "+f"(d[2]), "+f"(d[3])
        : "r"(a[0]), "r"(a[1]), "r"(a[2]), "r"(a[3]), "r"(b[0]), "r"(b[1]));
}
#define LDSM4(R, addr) \
    asm volatile("ldmatrix.sync.aligned.m8n8.x4.shared.b16 {%0,%1,%2,%3}, [%4];" \
        : "=r"((R)[0]), "=r"((R)[1]), "=r"((R)[2]), "=r"((R)[3]) : "r"(addr))

// ============================================================================
// k_down: partial h = x @ w_down^T over K-chunk (640 each)
// R14 structure; MMA stream reordered TERM-MAJOR (same-acc reuse distance 4).
// grid (16 s, 2 kc, 8 b) = 256 CTAs, 256 thr.
// ============================================================================
static constexpr int D_T   = 64 * LDP;            // elems per tile (4608)
static constexpr int D_BUF = 4 * D_T;             // AH AL WH WL
static constexpr int SMEM_DOWN = 2 * D_BUF * 2;   // 73728 B

__global__ __launch_bounds__(256, 2)
void k_down(const float* __restrict__ x, const float* __restrict__ embed) {
    extern __shared__ __nv_bfloat16 sm[];
    const uint32_t smb = smem_u32(sm);
    const int tid = threadIdx.x, lane = tid & 31, wid = tid >> 5;
    const int b = blockIdx.z, kcb = blockIdx.y, s0 = blockIdx.x * 64;
    const int kbase = kcb * 640;
    const float* __restrict__ xb = x     + ((size_t)b * SQ + s0) * DIN + kbase;
    const float* __restrict__ wd = embed + (size_t)b * EMBSZ + kbase;   // [r][DIN] fp32

    const int frow = tid >> 4, fcol = (tid & 15) * 4;
    const int wm = wid >> 1, wn = wid & 1;
    const int m0 = wm * 16, n0 = wn * 32;
    const int r8 = lane & 7, gq = lane >> 3;

    const uint32_t offA  = (uint32_t)(m0 + r8 + (gq & 1) * 8) * LDPB + (gq >> 1) * 16;
    const uint32_t offB0 = (uint32_t)(n0 + 0 * 8 + r8 + (gq >> 1) * 8) * LDPB + (gq & 1) * 16;
    const uint32_t offB2 = (uint32_t)(n0 + 2 * 8 + r8 + (gq >> 1) * 8) * LDPB + (gq & 1) * 16;

    float acc[4][4];
#pragma unroll
    for (int u = 0; u < 4; u++)
#pragma unroll
        for (int j = 0; j < 4; j++) acc[u][j] = 0.f;

    {
        __nv_bfloat16* AH = sm;           __nv_bfloat16* AL = sm + D_T;
        __nv_bfloat16* WH = sm + 2 * D_T; __nv_bfloat16* WL = sm + 3 * D_T;
#pragma unroll
        for (int p = 0; p < 4; p++) {
            const int row = p * 16 + frow;
            float4 v = *(const float4*)(xb + (size_t)row * DIN + fcol);
            uint32_t h0, l0, h1, l1;
            split2f(v.x, v.y, h0, l0); split2f(v.z, v.w, h1, l1);
            *(uint2*)(AH + row * LDP + fcol) = make_uint2(h0, h1);
            *(uint2*)(AL + row * LDP + fcol) = make_uint2(l0, l1);
            float4 w = *(const float4*)(wd + (size_t)row * DIN + fcol);
            split2f(w.x, w.y, h0, l0); split2f(w.z, w.w, h1, l1);
            *(uint2*)(WH + row * LDP + fcol) = make_uint2(h0, h1);
            *(uint2*)(WL + row * LDP + fcol) = make_uint2(l0, l1);
        }
    }
    __syncthreads();

    for (int it = 0; it < 10; it++) {
        const uint32_t base = smb + (it & 1) * (D_BUF * 2);
        const bool has_next = (it + 1 < 10);
        const int kc = (it + 1) * 64;
        __nv_bfloat16* nb = sm + ((it + 1) & 1) * D_BUF;

        float4 xv[4];
        if (has_next) {
#pragma unroll
            for (int p = 0; p < 4; p++)
                xv[p] = *(const float4*)(xb + (size_t)(p * 16 + frow) * DIN + kc + fcol);
        }

        const uint32_t AH = base, AL = base + 2 * D_T, WH = base + 4 * D_T, WL = base + 6 * D_T;
#pragma unroll
        for (int kk = 0; kk < 2; kk++) {
            const uint32_t ko = kk * 32;
            uint32_t aH[4], aL[4], bH[4], bL[4], bH2[4], bL2[4];
            LDSM4(aH, AH + offA + ko);
            LDSM4(aL, AL + offA + ko);
            LDSM4(bH, WH + offB0 + ko);
            LDSM4(bL, WL + offB0 + ko);
            LDSM4(bH2, WH + offB2 + ko);
            LDSM4(bL2, WL + offB2 + ko);
            // term-major: same-acc reuse distance = 4
            mma16816(acc[0], aH, bH);     mma16816(acc[1], aH, bH + 2);
            mma16816(acc[2], aH, bH2);    mma16816(acc[3], aH, bH2 + 2);
            mma16816(acc[0], aH, bL);     mma16816(acc[1], aH, bL + 2);
            mma16816(acc[2], aH, bL2);    mma16816(acc[3], aH, bL2 + 2);
            mma16816(acc[0], aL, bH);     mma16816(acc[1], aL, bH + 2);
            mma16816(acc[2], aL, bH2);    mma16816(acc[3], aL, bH2 + 2);
        }

        float4 wv[4];
        if (has_next) {
            __nv_bfloat16* AHn = nb; __nv_bfloat16* ALn = nb + D_T;
#pragma unroll
            for (int p = 0; p < 4; p++) {
                const int row = p * 16 + frow;
                uint32_t h0, l0, h1, l1;
                split2f(xv[p].x, xv[p].y, h0, l0); split2f(xv[p].z, xv[p].w, h1, l1);
                *(uint2*)(AHn + row * LDP + fcol) = make_uint2(h0, h1);
                *(uint2*)(ALn + row * LDP + fcol) = make_uint2(l0, l1);
            }
#pragma unroll
            for (int p = 0; p < 4; p++)
                wv[p] = *(const float4*)(wd + (size_t)(p * 16 + frow) * DIN + kc + fcol);
        }

#pragma unroll
        for (int kk = 2; kk < 4; kk++) {
            const uint32_t ko = kk * 32;
            uint32_t aH[4], aL[4], bH[4], bL[4], bH2[4], bL2[4];
            LDSM4(aH, AH + offA + ko);
            LDSM4(aL, AL + offA + ko);
            LDSM4(bH, WH + offB0 + ko);
            LDSM4(bL, WL + offB0 + ko);
            LDSM4(bH2, WH + offB2 + ko);
            LDSM4(bL2, WL + offB2 + ko);
            mma16816(acc[0], aH, bH);     mma16816(acc[1], aH, bH + 2);
            mma16816(acc[2], aH, bH2);    mma16816(acc[3], aH, bH2 + 2);
            mma16816(acc[0], aH, bL);     mma16816(acc[1], aH, bL + 2);
            mma16816(acc[2], aH, bL2);    mma16816(acc[3], aH, bL2 + 2);
            mma16816(acc[0], aL, bH);     mma16816(acc[1], aL, bH + 2);
            mma16816(acc[2], aL, bH2);    mma16816(acc[3], aL, bH2 + 2);
        }

        if (has_next) {
            __nv_bfloat16* WHn = nb + 2 * D_T; __nv_bfloat16* WLn = nb + 3 * D_T;
#pragma unroll
            for (int p = 0; p < 4; p++) {
                const int row = p * 16 + frow;
                uint32_t h0, l0, h1, l1;
                split2f(wv[p].x, wv[p].y, h0, l0); split2f(wv[p].z, wv[p].w, h1, l1);
                *(uint2*)(WHn + row * LDP + fcol) = make_uint2(h0, h1);
                *(uint2*)(WLn + row * LDP + fcol) = make_uint2(l0, l1);
            }
            __syncthreads();
        }
    }

    float* hp = g_hp[kcb] + ((size_t)b * SQ + s0) * RNK;
    const int g = lane >> 2, tg = lane & 3;
#pragma unroll
    for (int u = 0; u < 4; u++) {
        const int c = n0 + u * 8 + tg * 2;
        *(float2*)(hp + (size_t)(m0 + g) * RNK + c)     = make_float2(acc[u][0], acc[u][1]);
        *(float2*)(hp + (size_t)(m0 + g + 8) * RNK + c) = make_float2(acc[u][2], acc[u][3]);
    }
}

// ============================================================================
// k_up: R14 structure (grid 16x10x8, 22.0us known); MMA stream reordered
// TERM-MAJOR across t and u (same-acc reuse distance 8).
// ============================================================================
static constexpr int U_HT = 64 * LDP;
static constexpr int U_WT = 128 * LDP;
static constexpr int SMEM_UP = (2 * U_HT + 2 * U_WT) * 2;  // 55296 B

__global__ __launch_bounds__(256, 2)
void k_up(const float* __restrict__ embed, float* __restrict__ out) {
    extern __shared__ __nv_bfloat16 sm[];
    __nv_bfloat16* HH = sm;
    __nv_bfloat16* HL = sm + U_HT;
    __nv_bfloat16* WH = sm + 2 * U_HT;
    __nv_bfloat16* WL = sm + 2 * U_HT + U_WT;
    const uint32_t smb = smem_u32(sm);

    const int tid = threadIdx.x, lane = tid & 31, wid = tid >> 5;
    const int b = blockIdx.z, s0 = blockIdx.x * 64, o0 = blockIdx.y * 128;
    const float* __restrict__ h0p = g_hp[0] + ((size_t)b * SQ + s0) * RNK;
    const float* __restrict__ h1p = g_hp[1] + ((size_t)b * SQ + s0) * RNK;
    const float* __restrict__ wp  = embed + (size_t)b * EMBSZ + DOWNSZ
                                    + (size_t)o0 * RNK;              // [o][r] fp32

    const int frow = tid >> 4, fcol = (tid & 15) * 4;
#pragma unroll
    for (int p = 0; p < 8; p++) {
        const int row = p * 16 + frow;
        float4 v = *(const float4*)(wp + (size_t)row * RNK + fcol);
        uint32_t h0, l0, h1, l1;
        split2f(v.x, v.y, h0, l0); split2f(v.z, v.w, h1, l1);
        *(uint2*)(WH + row * LDP + fcol) = make_uint2(h0, h1);
        *(uint2*)(WL + row * LDP + fcol) = make_uint2(l0, l1);
    }
#pragma unroll
    for (int p = 0; p < 4; p++) {
        const int row = p * 16 + frow;
        float4 a = *(const float4*)(h0p + (size_t)row * RNK + fcol);
        float4 c = *(const float4*)(h1p + (size_t)row * RNK + fcol);
        uint32_t h0, l0, h1, l1;
        split2f(a.x + c.x, a.y + c.y, h0, l0);
        split2f(a.z + c.z, a.w + c.w, h1, l1);
        *(uint2*)(HH + row * LDP + fcol) = make_uint2(h0, h1);
        *(uint2*)(HL + row * LDP + fcol) = make_uint2(l0, l1);
    }
    __syncthreads();

    const int wm = wid >> 2, wn = wid & 3;
    const int m0 = wm * 32, n0 = wn * 32;
    const int r8 = lane & 7, gq = lane >> 3;

    const uint32_t HHa = smb, HLa = smb + U_HT * 2;
    const uint32_t WHa = smb + 4 * U_HT, WLa = smb + 4 * U_HT + 2 * U_WT;
    const uint32_t offA0 = (uint32_t)(m0 + r8 + (gq & 1) * 8) * LDPB + (gq >> 1) * 16;
    const uint32_t offA1 = offA0 + 16 * LDPB;
    const uint32_t offB0 = (uint32_t)(n0 + r8 + (gq >> 1) * 8) * LDPB + (gq & 1) * 16;
    const uint32_t offB2 = offB0 + 16 * LDPB;

    float acc[2][4][4];
#pragma unroll
    for (int t = 0; t < 2; t++)
#pragma unroll
        for (int u = 0; u < 4; u++)
#pragma unroll
            for (int j = 0; j < 4; j++) acc[t][u][j] = 0.f;

#pragma unroll
    for (int kk = 0; kk < 4; kk++) {
        const uint32_t ko = kk * 32;
        uint32_t aH0[4], aL0[4], aH1[4], aL1[4];
        uint32_t bH[4], bL[4], bH2[4], bL2[4];
        LDSM4(aH0, HHa + offA0 + ko);
        LDSM4(aL0, HLa + offA0 + ko);
        LDSM4(aH1, HHa + offA1 + ko);
        LDSM4(aL1, HLa + offA1 + ko);
        LDSM4(bH, WHa + offB0 + ko);
        LDSM4(bL, WLa + offB0 + ko);
        LDSM4(bH2, WHa + offB2 + ko);
        LDSM4(bL2, WLa + offB2 + ko);
        // term-major across t,u: same-acc reuse distance = 8
#pragma unroll
        for (int t = 0; t < 2; t++) {
            const uint32_t* aH = t ? aH1 : aH0;
            mma16816(acc[t][0], aH, bH);     mma16816(acc[t][1], aH, bH + 2);
            mma16816(acc[t][2], aH, bH2);    mma16816(acc[t][3], aH, bH2 + 2);
        }
#pragma unroll
        for (int t = 0; t < 2; t++) {
            const uint32_t* aH = t ? aH1 : aH0;
            mma16816(acc[t][0], aH, bL);     mma16816(acc[t][1], aH, bL + 2);
            mma16816(acc[t][2], aH, bL2);    mma16816(acc[t][3], aH, bL2 + 2);
        }
#pragma unroll
        for (int t = 0; t < 2; t++) {
            const uint32_t* aL = t ? aL1 : aL0;
            mma16816(acc[t][0], aL, bH);     mma16816(acc[t][1], aL, bH + 2);
            mma16816(acc[t][2], aL, bH2);    mma16816(acc[t][3], aL, bH2 + 2);
        }
    }

    const int g = lane >> 2, tg = lane & 3;
#pragma unroll
    for (int t = 0; t < 2; t++) {
        const size_t r0 = (size_t)b * SQ + s0 + m0 + t * 16 + g;
#pragma unroll
        for (int u = 0; u < 4; u++) {
            const int c = o0 + n0 + u * 8 + tg * 2;
            *(float2*)(out + r0 * DOUT + c)       = make_float2(acc[t][u][0], acc[t][u][1]);
            *(float2*)(out + (r0 + 8) * DOUT + c) = make_float2(acc[t][u][2], acc[t][u][3]);
        }
    }
}

extern "C" void kernel_launch(void* const* d_in, const int* in_sizes, int n_in,
                              void* d_out, int out_size) {
    const float* x     = (const float*)d_in[0];   // [8,1024,1280]
    const float* embed = (const float*)d_in[1];   // [8,163840]
    float*       out   = (float*)d_out;           // [8,1024,1280]
    (void)in_sizes; (void)n_in; (void)out_size;

    cudaFuncSetAttribute(k_down, cudaFuncAttributeMaxDynamicSharedMemorySize, SMEM_DOWN);
    cudaFuncSetAttribute(k_up,   cudaFuncAttributeMaxDynamicSharedMemorySize, SMEM_UP);

    k_down<<<dim3(16, 2, 8), 256, SMEM_DOWN>>>(x, embed);
    k_up<<<dim3(16, 10, 8), 256, SMEM_UP>>>(embed, out);
}